// round 14
// baseline (speedup 1.0000x reference)
#include <cuda_runtime.h>
#include <cuda_fp16.h>
#include <cstdint>

// Problem constants
#define B_    4
#define S_    2048
#define H_    8
#define BH_   (B_*H_)       // 32

// log2(e) folded into q/pos_q at projection time (softmax in exp2 domain)
#define LOG2E_F      1.4426950408889634f
#define QSCALE_F     0.36067376022224085f   // 0.25 * log2(e)

// Packed split-fp16 intermediates (static device scratch)
__device__ __align__(256) __half Qpack_d[(size_t)BH_ * S_ * 64];  // [bh][s][Qh(32)|Ql(32)]
__device__ __align__(256) __half Kpack_d[(size_t)BH_ * S_ * 64];  // [bh][key][Kh(32)|Kl(32)]
__device__ __align__(256) __half Vh_d[(size_t)BH_ * 16 * S_];     // [bh][vd][key]
__device__ __align__(256) float  Od_d[(size_t)BH_ * S_ * 16];     // [bh][s][16]
__device__ __align__(256) __half Wsplit_d[4][128][2][128];        // [w][o][hi/lo][k]

// ---------------------------------------------------------------------------
// PTX helpers (baseline features only — compute_103-safe)
// ---------------------------------------------------------------------------
__device__ __forceinline__ uint32_t smem_u32(const void* p) {
    uint32_t a;
    asm("{ .reg .u64 t; cvta.to.shared.u64 t, %1; cvt.u32.u64 %0, t; }" : "=r"(a) : "l"(p));
    return a;
}
__device__ __forceinline__ void cp16(uint32_t d, const void* s) {
    asm volatile("cp.async.cg.shared.global [%0], [%1], 16;" :: "r"(d), "l"(s));
}
#define CP_COMMIT() asm volatile("cp.async.commit_group;" ::: "memory")
#define CP_WAIT1()  asm volatile("cp.async.wait_group 1;" ::: "memory")
#define CP_WAIT0()  asm volatile("cp.async.wait_group 0;" ::: "memory")

__device__ __forceinline__ void ldm4(uint32_t* r, uint32_t addr) {
    asm volatile("ldmatrix.sync.aligned.m8n8.x4.shared.b16 {%0,%1,%2,%3}, [%4];"
        : "=r"(r[0]), "=r"(r[1]), "=r"(r[2]), "=r"(r[3]) : "r"(addr));
}
__device__ __forceinline__ void mma16816(float* d, const uint32_t* a, const uint32_t* b) {
    asm volatile("mma.sync.aligned.m16n8k16.row.col.f32.f16.f16.f32 "
        "{%0,%1,%2,%3}, {%4,%5,%6,%7}, {%8,%9}, {%0,%1,%2,%3};"
        : "+f"(d[0]), "+f"(d[1]), "+f"(d[2]), "+f"(d[3])
        : "r"(a[0]), "r"(a[1]), "r"(a[2]), "r"(a[3]), "r"(b[0]), "r"(b[1]));
}
__device__ __forceinline__ float ex2(float x) {
    float y;
    asm("ex2.approx.ftz.f32 %0, %1;" : "=f"(y) : "f"(x));
    return y;
}
// packed half2 exp2 — one MUFU for two P values, result already in mma layout
__device__ __forceinline__ uint32_t ex2h2(uint32_t x) {
    uint32_t y;
    asm("ex2.approx.f16x2 %0, %1;" : "=r"(y) : "r"(x));
    return y;
}

#define SWZ(x) ((x) ^ (((x) >> 3) & 0x70))

__device__ __forceinline__ void split2(float x, __half& hi, __half& lo) {
    hi = __float2half_rn(x);
    lo = __float2half_rn(x - __half2float(hi));
}
__device__ __forceinline__ uint32_t pack2(__half a, __half b) {
    __half2 t = __halves2half2(a, b);
    return *reinterpret_cast<uint32_t*>(&t);
}
__device__ __forceinline__ uint32_t packf2(float a, float b) {
    __half2 t = __floats2half2_rn(a, b);
    return *reinterpret_cast<uint32_t*>(&t);
}

// ---------------------------------------------------------------------------
// Kernel 0: split W0/W1/W2/Wo into fp16 hi/lo pairs.
// ---------------------------------------------------------------------------
__global__ void __launch_bounds__(256) prep_kernel(
    const float* __restrict__ W0, const float* __restrict__ W1,
    const float* __restrict__ W2, const float* __restrict__ Wo)
{
    const int idx = blockIdx.x * 256 + threadIdx.x;   // 0 .. 65535
    const int w = idx >> 14;
    const int o = (idx >> 7) & 127;
    const int k = idx & 127;
    const float* W = (w == 0) ? W0 : (w == 1) ? W1 : (w == 2) ? W2 : Wo;
    __half hi, lo;
    split2(W[o * 128 + k], hi, lo);
    Wsplit_d[w][o][0][k] = hi;
    Wsplit_d[w][o][1][k] = lo;
}

// ---------------------------------------------------------------------------
// Kernel 1: HMMA projections (split-fp16, 3 chains).
//   p=0: query@W0^T *0.25*log2e -> Q dims 0-15   p=1: pos@W0^T *log2e -> Q dims 16-31
//   p=2: key  @W1^T             -> K dims 0-15   p=3: pos@W1^T        -> K dims 16-31
//   p=4: value@W2^T             -> Vh (transposed, hi only)
// ---------------------------------------------------------------------------
__global__ void __launch_bounds__(256) proj_kernel(
    const float* __restrict__ query, const float* __restrict__ key,
    const float* __restrict__ value, const float* __restrict__ pos,
    const float* __restrict__ b0, const float* __restrict__ b1,
    const float* __restrict__ b2)
{
    __shared__ __align__(1024) __half Xh[64 * 64];    // 64 rows x 128B
    __shared__ __align__(1024) __half Xl[64 * 64];
    __shared__ __align__(1024) __half Wh[128 * 64];   // 128 o x 128B
    __shared__ __align__(1024) __half Wl[128 * 64];

    const int p = blockIdx.y;
    const float* X = (p == 0) ? query : (p == 1 || p == 3) ? pos : (p == 2) ? key : value;
    const float* bias = (p < 2) ? b0 : (p < 4) ? b1 : b2;
    const int wsel = (p < 2) ? 0 : (p < 4) ? 1 : 2;

    const int row0 = blockIdx.x * 64;
    const int tid  = threadIdx.x;
    const int warp = tid >> 5;
    const int lane = tid & 31;
    const int grp  = lane >> 3;
    const int wi   = lane & 7;

    const uint32_t xh = smem_u32(Xh), xl = smem_u32(Xl);
    const uint32_t wh = smem_u32(Wh), wl = smem_u32(Wl);

    const int mrow0 = (warp >> 1) * 16;     // warp row base within tile
    const int ncol0 = (warp & 1) * 64;      // warp col base

    float C[8][4];
#pragma unroll
    for (int nb = 0; nb < 8; nb++)
#pragma unroll
        for (int j = 0; j < 4; j++) C[nb][j] = 0.f;

    for (int kc = 0; kc < 2; kc++) {
        __syncthreads();
#pragma unroll
        for (int it = 0; it < 4; it++) {
            const int e = tid + it * 256;            // 0..1023
            const int o = e >> 3, c = e & 7;
            cp16(wh + 2 * SWZ(o * 64 + c * 8), &Wsplit_d[wsel][o][0][kc * 64 + c * 8]);
            cp16(wl + 2 * SWZ(o * 64 + c * 8), &Wsplit_d[wsel][o][1][kc * 64 + c * 8]);
        }
#pragma unroll
        for (int it = 0; it < 4; it++) {
            const int e = tid + it * 256;            // 0..1023 float4s
            const int row = e >> 4, c4 = e & 15;
            const float4 v = *(const float4*)(X + (size_t)(row0 + row) * 128 + kc * 64 + c4 * 4);
            __half h0, h1, h2, h3, l0, l1, l2, l3;
            split2(v.x, h0, l0); split2(v.y, h1, l1);
            split2(v.z, h2, l2); split2(v.w, h3, l3);
            uint2 hp, lp;
            hp.x = pack2(h0, h1);  hp.y = pack2(h2, h3);
            lp.x = pack2(l0, l1);  lp.y = pack2(l2, l3);
            const uint32_t off = 2 * SWZ(row * 64 + c4 * 4);
            *(uint2*)((char*)Xh + off) = hp;
            *(uint2*)((char*)Xl + off) = lp;
        }
        CP_COMMIT(); CP_WAIT0();
        __syncthreads();

#pragma unroll
        for (int t = 0; t < 4; t++) {
            uint32_t Ah[4], Al[4];
            const uint32_t arow = mrow0 + (grp & 1) * 8 + wi;
            const uint32_t acol = t * 16 + (grp >> 1) * 8;
            ldm4(Ah, xh + 2 * SWZ(arow * 64 + acol));
            ldm4(Al, xl + 2 * SWZ(arow * 64 + acol));
#pragma unroll
            for (int pb = 0; pb < 4; pb++) {
                const uint32_t orow = ncol0 + pb * 16 + (grp >> 1) * 8 + wi;
                const uint32_t ocol = t * 16 + (grp & 1) * 8;
                uint32_t Bh[4], Bl[4];
                ldm4(Bh, wh + 2 * SWZ(orow * 64 + ocol));
                mma16816(C[2 * pb],     Ah, Bh);
                mma16816(C[2 * pb + 1], Ah, Bh + 2);
                mma16816(C[2 * pb],     Al, Bh);
                mma16816(C[2 * pb + 1], Al, Bh + 2);
                ldm4(Bl, wl + 2 * SWZ(orow * 64 + ocol));
                mma16816(C[2 * pb],     Ah, Bl);
                mma16816(C[2 * pb + 1], Ah, Bl + 2);
            }
        }
    }

    // ---- epilogue: bias, scale (log2e folded), split, scatter ----
    const int bb = row0 >> 11;
#pragma unroll
    for (int half = 0; half < 2; half++) {
        const int row = row0 + mrow0 + (lane >> 2) + half * 8;
        const int s   = row & 2047;
#pragma unroll
        for (int nb = 0; nb < 8; nb++) {
            const int col = ncol0 + nb * 8 + (lane & 3) * 2;
            float y0 = C[nb][2 * half]     + __ldg(bias + col);
            float y1 = C[nb][2 * half + 1] + __ldg(bias + col + 1);
            if (p == 0) { y0 *= QSCALE_F; y1 *= QSCALE_F; }
            else if (p == 1) { y0 *= LOG2E_F; y1 *= LOG2E_F; }
            __half h0, h1, l0, l1;
            split2(y0, h0, l0); split2(y1, h1, l1);
            const int hh = col >> 4, dd = col & 15;
            const size_t bhrow = ((size_t)(bb * H_ + hh) * S_ + s);
            const uint32_t hp = pack2(h0, h1);
            const uint32_t lp = pack2(l0, l1);
            switch (p) {
                case 0:
                    *(uint32_t*)(Qpack_d + bhrow * 64 + dd)      = hp;
                    *(uint32_t*)(Qpack_d + bhrow * 64 + 32 + dd) = lp;
                    break;
                case 1:
                    *(uint32_t*)(Qpack_d + bhrow * 64 + 16 + dd) = hp;
                    *(uint32_t*)(Qpack_d + bhrow * 64 + 48 + dd) = lp;
                    break;
                case 2:
                    *(uint32_t*)(Kpack_d + bhrow * 64 + dd)      = hp;
                    *(uint32_t*)(Kpack_d + bhrow * 64 + 32 + dd) = lp;
                    break;
                case 3:
                    *(uint32_t*)(Kpack_d + bhrow * 64 + 16 + dd) = hp;
                    *(uint32_t*)(Kpack_d + bhrow * 64 + 48 + dd) = lp;
                    break;
                default: {
                    const size_t vi0 = ((size_t)(bb * H_ + hh) * 16 + dd) * S_ + s;
                    const size_t vi1 = ((size_t)(bb * H_ + hh) * 16 + dd + 1) * S_ + s;
                    Vh_d[vi0] = h0; Vh_d[vi1] = h1;
                } break;
            }
        }
    }
}

// ---------------------------------------------------------------------------
// Kernel 2: HMMA flash attention — 32-key tiles for 3 CTAs/SM spill-free.
// Sc halves to 16 regs (Sc[4][4]); total regs ~70 < 85 cap of (256,3).
// Q staged in ring space (overlay), consumed into Aq regs, rings reuse bytes.
// smem/CTA = 16.5KB -> 3 CTAs/SM; regs fit -> no spills (unlike R13).
// QK: hh + lh fp32-acc (16 mma/tile).  PV: Ph*Vh + ones-frag Lc (6 mma/tile).
// Softmax: fp32 exact max; P = ex2.approx.f16x2.  64 tiles of 32 keys.
// ---------------------------------------------------------------------------
__global__ void __launch_bounds__(256, 3) flash_kernel()
{
    // Unified buffer:
    //   prologue: Q tile occupies [0, 16384)
    //   mainloop: K0 [0,4096) K1 [4096,8192) V0 [8192,10240) V1 [10240,12288)
    //   (K rows 128B stride, Kh 64B used; V rows 128B stride, 64B used)
    __shared__ __align__(1024) char Smem[16640];

    const int qt = blockIdx.x;
    const int bh = blockIdx.y;
    const int tid  = threadIdx.x;
    const int warp = tid >> 5;
    const int lane = tid & 31;
    const int grp  = lane >> 3;
    const int wi   = lane & 7;

    const uint32_t sbase = smem_u32(Smem);
    const uint32_t ksb[2] = { sbase,        sbase + 4096 };
    const uint32_t vhb[2] = { sbase + 8192, sbase + 10240 };

    const __half* Kg0 = Kpack_d + (size_t)bh * S_ * 64;
    const __half* Vg0 = Vh_d + ((size_t)bh * 16) * S_;

    // constant B-fragment of the "ones column" (n=0 holders are lanes 0-3)
    const uint32_t onesv = (lane < 4) ? 0x3C003C00u : 0u;
    const uint32_t bones[2] = { onesv, onesv };

    // ---- stage 1: Q into ring space, consume into registers ----
    {
        const __half* Qg = Qpack_d + ((size_t)bh * S_ + (size_t)qt * 128) * 64;
#pragma unroll
        for (int i = 0; i < 4; i++) {
            int e = tid + i * 256;
            cp16(sbase + SWZ((e >> 3) * 128 + (e & 7) * 16), Qg + (size_t)e * 8);
        }
        CP_COMMIT(); CP_WAIT0();
        __syncthreads();
    }

    uint32_t Aq[4][4];
#pragma unroll
    for (int t = 0; t < 4; t++) {
        const int row = warp * 16 + (grp & 1) * 8 + wi;
        const int ch  = t * 16 + (grp >> 1) * 8;
        ldm4(Aq[t], sbase + SWZ(row * 128 + ch * 2));
    }
    __syncthreads();     // every warp done reading Q before rings overwrite it

    // ---- stage 2: prefetch K/V 32-key tiles 0,1 ----
#pragma unroll
    for (int pre = 0; pre < 2; pre++) {
        const __half* Kg = Kg0 + (size_t)pre * 32 * 64;
        if (tid < 128) {       // Kh: 32 rows x 64B = 128 x 16B
            int r = tid >> 2, c = tid & 3;
            cp16(ksb[pre] + SWZ(r * 128 + c * 16), Kg + (size_t)r * 64 + c * 8);
        } else if (tid < 192) { // V: 16 rows x 64B = 64 x 16B
            int t2 = tid - 128;
            int r = t2 >> 2, c = t2 & 3;
            cp16(vhb[pre] + SWZ(r * 128 + c * 16),
                 Vg0 + (size_t)r * S_ + (size_t)pre * 32 + c * 8);
        }
        CP_COMMIT();
    }

    CP_WAIT1();          // tile0 resident
    __syncthreads();

    float m0 = -1e30f, m1 = -1e30f;
    float Oc[2][4], Lc[4];
#pragma unroll
    for (int nb = 0; nb < 2; nb++)
#pragma unroll
        for (int j = 0; j < 4; j++) Oc[nb][j] = 0.f;
#pragma unroll
    for (int j = 0; j < 4; j++) Lc[j] = 0.f;

    for (int kt = 0; kt < S_ / 32; kt++) {
        const int buf = kt & 1;
        const uint32_t kss = ksb[buf];

        float Sc[4][4];
#pragma unroll
        for (int nb = 0; nb < 4; nb++)
#pragma unroll
            for (int j = 0; j < 4; j++) Sc[nb][j] = 0.f;

        // --- S = Qh*Kh + Ql*Kh over 32 keys ---
#pragma unroll
        for (int t = 0; t < 2; t++) {
#pragma unroll
            for (int p = 0; p < 2; p++) {
                const int key = p * 16 + (grp >> 1) * 8 + wi;
                uint32_t kb[4];
                ldm4(kb, kss + SWZ(key * 128 + (t * 16 + (grp & 1) * 8) * 2));
                mma16816(Sc[2 * p],     Aq[t],     kb);
                mma16816(Sc[2 * p + 1], Aq[t],     kb + 2);
                mma16816(Sc[2 * p],     Aq[t + 2], kb);
                mma16816(Sc[2 * p + 1], Aq[t + 2], kb + 2);
            }
        }

        // --- online softmax: exact fp32 row max over this 32-key tile ---
        float mx0 = -1e30f, mx1 = -1e30f;
#pragma unroll
        for (int nb = 0; nb < 4; nb++) {
            mx0 = fmaxf(mx0, fmaxf(Sc[nb][0], Sc[nb][1]));
            mx1 = fmaxf(mx1, fmaxf(Sc[nb][2], Sc[nb][3]));
        }
        mx0 = fmaxf(mx0, __shfl_xor_sync(0xffffffffu, mx0, 1));
        mx0 = fmaxf(mx0, __shfl_xor_sync(0xffffffffu, mx0, 2));
        mx1 = fmaxf(mx1, __shfl_xor_sync(0xffffffffu, mx1, 1));
        mx1 = fmaxf(mx1, __shfl_xor_sync(0xffffffffu, mx1, 2));

        const float mn0 = fmaxf(m0, mx0), mn1 = fmaxf(m1, mx1);
        const float c0 = ex2(m0 - mn0), c1 = ex2(m1 - mn1);
        m0 = mn0; m1 = mn1;

#pragma unroll
        for (int nb = 0; nb < 2; nb++) {
            Oc[nb][0] *= c0; Oc[nb][1] *= c0;
            Oc[nb][2] *= c1; Oc[nb][3] *= c1;
        }
        Lc[0] *= c0; Lc[2] *= c1;      // only cols held by lane&3==0 matter

        // --- P = exp2(S-m) via f16x2; O += P*Vh ; Lc += P*ones ---
        const int vrow = (grp >> 1) * 8 + wi;
#pragma unroll
        for (int k2 = 0; k2 < 2; k2++) {
            uint32_t Pa[4];
#pragma unroll
            for (int h = 0; h < 2; h++) {
                const int nb = 2 * k2 + h;
                Pa[2 * h]     = ex2h2(packf2(Sc[nb][0] - mn0, Sc[nb][1] - mn0));
                Pa[2 * h + 1] = ex2h2(packf2(Sc[nb][2] - mn1, Sc[nb][3] - mn1));
            }
            uint32_t vb[4];
            ldm4(vb, vhb[buf] + SWZ(vrow * 128 + (k2 * 16 + (grp & 1) * 8) * 2));
            mma16816(Oc[0], Pa, vb);
            mma16816(Oc[1], Pa, vb + 2);
            mma16816(Lc, Pa, bones);
        }

        __syncthreads();
        if (kt + 2 < S_ / 32) {
            const __half* Kg = Kg0 + (size_t)(kt + 2) * 32 * 64;
            if (tid < 128) {
                int r = tid >> 2, c = tid & 3;
                cp16(ksb[buf] + SWZ(r * 128 + c * 16), Kg + (size_t)r * 64 + c * 8);
            } else if (tid < 192) {
                int t2 = tid - 128;
                int r = t2 >> 2, c = t2 & 3;
                cp16(vhb[buf] + SWZ(r * 128 + c * 16),
                     Vg0 + (size_t)r * S_ + (size_t)(kt + 2) * 32 + c * 8);
            }
        }
        CP_COMMIT();
        if (kt + 1 < S_ / 32) {
            CP_WAIT1();
            __syncthreads();
        }
    }

    {
        // l for each row sits in Lc[0]/Lc[2] of the quad's lane&3==0 thread
        const float lr0 = __shfl_sync(0xffffffffu, Lc[0], lane & ~3);
        const float lr1 = __shfl_sync(0xffffffffu, Lc[2], lane & ~3);
        const float i0 = 1.0f / lr0, i1 = 1.0f / lr1;
        const int r0 = qt * 128 + warp * 16 + (lane >> 2);
        const int r1 = r0 + 8;
#pragma unroll
        for (int nb = 0; nb < 2; nb++) {
            const int col = nb * 8 + (lane & 3) * 2;
            float2* d0 = (float2*)(Od_d + ((size_t)bh * S_ + r0) * 16 + col);
            float2* d1 = (float2*)(Od_d + ((size_t)bh * S_ + r1) * 16 + col);
            *d0 = make_float2(Oc[nb][0] * i0, Oc[nb][1] * i0);
            *d1 = make_float2(Oc[nb][2] * i1, Oc[nb][3] * i1);
        }
    }
}

// ---------------------------------------------------------------------------
// Kernel 3: HMMA output projection.  out = concat_heads(O) @ Wo^T + bo
// ---------------------------------------------------------------------------
__global__ void __launch_bounds__(256) outproj_kernel(
    const float* __restrict__ bo, float* __restrict__ out)
{
    __shared__ __align__(1024) __half Xh[64 * 64];
    __shared__ __align__(1024) __half Xl[64 * 64];
    __shared__ __align__(1024) __half Wh[128 * 64];
    __shared__ __align__(1024) __half Wl[128 * 64];

    const int row0 = blockIdx.x * 64;
    const int bb = row0 >> 11;
    const int s0 = row0 & 2047;

    const int tid  = threadIdx.x;
    const int warp = tid >> 5;
    const int lane = tid & 31;
    const int grp  = lane >> 3;
    const int wi   = lane & 7;

    const uint32_t xh = smem_u32(Xh), xl = smem_u32(Xl);
    const uint32_t wh = smem_u32(Wh), wl = smem_u32(Wl);

    const int mrow0 = (warp >> 1) * 16;
    const int ncol0 = (warp & 1) * 64;

    float C[8][4];
#pragma unroll
    for (int nb = 0; nb < 8; nb++)
#pragma unroll
        for (int j = 0; j < 4; j++) C[nb][j] = 0.f;

    for (int kc = 0; kc < 2; kc++) {
        __syncthreads();
#pragma unroll
        for (int it = 0; it < 4; it++) {
            const int e = tid + it * 256;
            const int o = e >> 3, c = e & 7;
            cp16(wh + 2 * SWZ(o * 64 + c * 8), &Wsplit_d[3][o][0][kc * 64 + c * 8]);
            cp16(wl + 2 * SWZ(o * 64 + c * 8), &Wsplit_d[3][o][1][kc * 64 + c * 8]);
        }
#pragma unroll
        for (int it = 0; it < 4; it++) {
            const int e = tid + it * 256;
            const int row = e >> 4, c4 = e & 15;
            const int col = kc * 64 + c4 * 4;
            const int hh = col >> 4, dd = col & 15;
            const float4 v = *(const float4*)(Od_d +
                (((size_t)(bb * H_ + hh) * S_) + s0 + row) * 16 + dd);
            __half h0, h1, h2, h3, l0, l1, l2, l3;
            split2(v.x, h0, l0); split2(v.y, h1, l1);
            split2(v.z, h2, l2); split2(v.w, h3, l3);
            uint2 hp, lp;
            hp.x = pack2(h0, h1);  hp.y = pack2(h2, h3);
            lp.x = pack2(l0, l1);  lp.y = pack2(l2, l3);
            const uint32_t off = 2 * SWZ(row * 64 + c4 * 4);
            *(uint2*)((char*)Xh + off) = hp;
            *(uint2*)((char*)Xl + off) = lp;
        }
        CP_COMMIT(); CP_WAIT0();
        __syncthreads();

#pragma unroll
        for (int t = 0; t < 4; t++) {
            uint32_t Ah[4], Al[4];
            const uint32_t arow = mrow0 + (grp & 1) * 8 + wi;
            const uint32_t acol = t * 16 + (grp >> 1) * 8;
            ldm4(Ah, xh + 2 * SWZ(arow * 64 + acol));
            ldm4(Al, xl + 2 * SWZ(arow * 64 + acol));
#pragma unroll
            for (int pb = 0; pb < 4; pb++) {
                const uint32_t orow = ncol0 + pb * 16 + (grp >> 1) * 8 + wi;
                const uint32_t ocol = t * 16 + (grp & 1) * 8;
                uint32_t Bh[4], Bl[4];
                ldm4(Bh, wh + 2 * SWZ(orow * 64 + ocol));
                mma16816(C[2 * pb],     Ah, Bh);
                mma16816(C[2 * pb + 1], Ah, Bh + 2);
                mma16816(C[2 * pb],     Al, Bh);
                mma16816(C[2 * pb + 1], Al, Bh + 2);
                ldm4(Bl, wl + 2 * SWZ(orow * 64 + ocol));
                mma16816(C[2 * pb],     Ah, Bl);
                mma16816(C[2 * pb + 1], Ah, Bl + 2);
            }
        }
    }

#pragma unroll
    for (int half = 0; half < 2; half++) {
        const int row = row0 + mrow0 + (lane >> 2) + half * 8;
#pragma unroll
        for (int nb = 0; nb < 8; nb++) {
            const int col = ncol0 + nb * 8 + (lane & 3) * 2;
            float2* dst = (float2*)(out + (size_t)row * 128 + col);
            *dst = make_float2(C[nb][2 * half]     + __ldg(bo + col),
                               C[nb][2 * half + 1] + __ldg(bo + col + 1));
        }
    }
}

// ---------------------------------------------------------------------------
extern "C" void kernel_launch(void* const* d_in, const int* in_sizes, int n_in,
                              void* d_out, int out_size)
{
    const float* query = (const float*)d_in[0];
    const float* key   = (const float*)d_in[1];
    const float* value = (const float*)d_in[2];
    const float* pos   = (const float*)d_in[3];
    const float* W0    = (const float*)d_in[4];
    const float* b0    = (const float*)d_in[5];
    const float* W1    = (const float*)d_in[6];
    const float* b1    = (const float*)d_in[7];
    const float* W2    = (const float*)d_in[8];
    const float* b2    = (const float*)d_in[9];
    const float* Wo    = (const float*)d_in[10];
    const float* bo    = (const float*)d_in[11];
    float* out = (float*)d_out;

    prep_kernel<<<256, 256>>>(W0, W1, W2, Wo);
    proj_kernel<<<dim3((B_ * S_) / 64, 5), 256>>>(query, key, value, pos, b0, b1, b2);
    flash_kernel<<<dim3(S_ / 128, BH_), 256>>>();
    outproj_kernel<<<(B_ * S_) / 64, 256>>>(bo, out);
}

// round 15
// speedup vs baseline: 1.0526x; 1.0526x over previous
#include <cuda_runtime.h>
#include <cuda_fp16.h>
#include <cstdint>

// Problem constants
#define B_    4
#define S_    2048
#define H_    8
#define BH_   (B_*H_)       // 32

// log2(e) folded into q/pos_q at projection time (softmax in exp2 domain)
#define LOG2E_F      1.4426950408889634f
#define QSCALE_F     0.36067376022224085f   // 0.25 * log2(e)

// Packed split-fp16 intermediates (static device scratch)
__device__ __align__(256) __half Qpack_d[(size_t)BH_ * S_ * 64];  // [bh][s][Qh(32)|Ql(32)]
__device__ __align__(256) __half Kpack_d[(size_t)BH_ * S_ * 64];  // [bh][key][Kh(32)|Kl(32)]
__device__ __align__(256) __half Vh_d[(size_t)BH_ * 16 * S_];     // [bh][vd][key]
__device__ __align__(256) float  Od_d[(size_t)BH_ * S_ * 16];     // [bh][s][16]
__device__ __align__(256) __half Wsplit_d[4][128][2][128];        // [w][o][hi/lo][k]

// ---------------------------------------------------------------------------
// PTX helpers (baseline features only — compute_103-safe)
// ---------------------------------------------------------------------------
__device__ __forceinline__ uint32_t smem_u32(const void* p) {
    uint32_t a;
    asm("{ .reg .u64 t; cvta.to.shared.u64 t, %1; cvt.u32.u64 %0, t; }" : "=r"(a) : "l"(p));
    return a;
}
__device__ __forceinline__ void cp16(uint32_t d, const void* s) {
    asm volatile("cp.async.cg.shared.global [%0], [%1], 16;" :: "r"(d), "l"(s));
}
#define CP_COMMIT() asm volatile("cp.async.commit_group;" ::: "memory")
#define CP_WAIT1()  asm volatile("cp.async.wait_group 1;" ::: "memory")
#define CP_WAIT0()  asm volatile("cp.async.wait_group 0;" ::: "memory")

__device__ __forceinline__ void ldm4(uint32_t* r, uint32_t addr) {
    asm volatile("ldmatrix.sync.aligned.m8n8.x4.shared.b16 {%0,%1,%2,%3}, [%4];"
        : "=r"(r[0]), "=r"(r[1]), "=r"(r[2]), "=r"(r[3]) : "r"(addr));
}
__device__ __forceinline__ void mma16816(float* d, const uint32_t* a, const uint32_t* b) {
    asm volatile("mma.sync.aligned.m16n8k16.row.col.f32.f16.f16.f32 "
        "{%0,%1,%2,%3}, {%4,%5,%6,%7}, {%8,%9}, {%0,%1,%2,%3};"
        : "+f"(d[0]), "+f"(d[1]), "+f"(d[2]), "+f"(d[3])
        : "r"(a[0]), "r"(a[1]), "r"(a[2]), "r"(a[3]), "r"(b[0]), "r"(b[1]));
}
__device__ __forceinline__ float ex2(float x) {
    float y;
    asm("ex2.approx.ftz.f32 %0, %1;" : "=f"(y) : "f"(x));
    return y;
}
// packed half2 exp2 — one MUFU for two P values, result already in mma layout
__device__ __forceinline__ uint32_t ex2h2(uint32_t x) {
    uint32_t y;
    asm("ex2.approx.f16x2 %0, %1;" : "=r"(y) : "r"(x));
    return y;
}

#define SWZ(x) ((x) ^ (((x) >> 3) & 0x70))

__device__ __forceinline__ void split2(float x, __half& hi, __half& lo) {
    hi = __float2half_rn(x);
    lo = __float2half_rn(x - __half2float(hi));
}
__device__ __forceinline__ uint32_t pack2(__half a, __half b) {
    __half2 t = __halves2half2(a, b);
    return *reinterpret_cast<uint32_t*>(&t);
}
__device__ __forceinline__ uint32_t packf2(float a, float b) {
    __half2 t = __floats2half2_rn(a, b);
    return *reinterpret_cast<uint32_t*>(&t);
}

// ---------------------------------------------------------------------------
// Kernel 0: split W0/W1/W2/Wo into fp16 hi/lo pairs.
// ---------------------------------------------------------------------------
__global__ void __launch_bounds__(256) prep_kernel(
    const float* __restrict__ W0, const float* __restrict__ W1,
    const float* __restrict__ W2, const float* __restrict__ Wo)
{
    const int idx = blockIdx.x * 256 + threadIdx.x;   // 0 .. 65535
    const int w = idx >> 14;
    const int o = (idx >> 7) & 127;
    const int k = idx & 127;
    const float* W = (w == 0) ? W0 : (w == 1) ? W1 : (w == 2) ? W2 : Wo;
    __half hi, lo;
    split2(W[o * 128 + k], hi, lo);
    Wsplit_d[w][o][0][k] = hi;
    Wsplit_d[w][o][1][k] = lo;
}

// ---------------------------------------------------------------------------
// Kernel 1: HMMA projections (split-fp16, 3 chains).
//   p=0: query@W0^T *0.25*log2e -> Q dims 0-15   p=1: pos@W0^T *log2e -> Q dims 16-31
//   p=2: key  @W1^T             -> K dims 0-15   p=3: pos@W1^T        -> K dims 16-31
//   p=4: value@W2^T             -> Vh (transposed, hi only)
// ---------------------------------------------------------------------------
__global__ void __launch_bounds__(256) proj_kernel(
    const float* __restrict__ query, const float* __restrict__ key,
    const float* __restrict__ value, const float* __restrict__ pos,
    const float* __restrict__ b0, const float* __restrict__ b1,
    const float* __restrict__ b2)
{
    __shared__ __align__(1024) __half Xh[64 * 64];    // 64 rows x 128B
    __shared__ __align__(1024) __half Xl[64 * 64];
    __shared__ __align__(1024) __half Wh[128 * 64];   // 128 o x 128B
    __shared__ __align__(1024) __half Wl[128 * 64];

    const int p = blockIdx.y;
    const float* X = (p == 0) ? query : (p == 1 || p == 3) ? pos : (p == 2) ? key : value;
    const float* bias = (p < 2) ? b0 : (p < 4) ? b1 : b2;
    const int wsel = (p < 2) ? 0 : (p < 4) ? 1 : 2;

    const int row0 = blockIdx.x * 64;
    const int tid  = threadIdx.x;
    const int warp = tid >> 5;
    const int lane = tid & 31;
    const int grp  = lane >> 3;
    const int wi   = lane & 7;

    const uint32_t xh = smem_u32(Xh), xl = smem_u32(Xl);
    const uint32_t wh = smem_u32(Wh), wl = smem_u32(Wl);

    const int mrow0 = (warp >> 1) * 16;     // warp row base within tile
    const int ncol0 = (warp & 1) * 64;      // warp col base

    float C[8][4];
#pragma unroll
    for (int nb = 0; nb < 8; nb++)
#pragma unroll
        for (int j = 0; j < 4; j++) C[nb][j] = 0.f;

    for (int kc = 0; kc < 2; kc++) {
        __syncthreads();
#pragma unroll
        for (int it = 0; it < 4; it++) {
            const int e = tid + it * 256;            // 0..1023
            const int o = e >> 3, c = e & 7;
            cp16(wh + 2 * SWZ(o * 64 + c * 8), &Wsplit_d[wsel][o][0][kc * 64 + c * 8]);
            cp16(wl + 2 * SWZ(o * 64 + c * 8), &Wsplit_d[wsel][o][1][kc * 64 + c * 8]);
        }
#pragma unroll
        for (int it = 0; it < 4; it++) {
            const int e = tid + it * 256;            // 0..1023 float4s
            const int row = e >> 4, c4 = e & 15;
            const float4 v = *(const float4*)(X + (size_t)(row0 + row) * 128 + kc * 64 + c4 * 4);
            __half h0, h1, h2, h3, l0, l1, l2, l3;
            split2(v.x, h0, l0); split2(v.y, h1, l1);
            split2(v.z, h2, l2); split2(v.w, h3, l3);
            uint2 hp, lp;
            hp.x = pack2(h0, h1);  hp.y = pack2(h2, h3);
            lp.x = pack2(l0, l1);  lp.y = pack2(l2, l3);
            const uint32_t off = 2 * SWZ(row * 64 + c4 * 4);
            *(uint2*)((char*)Xh + off) = hp;
            *(uint2*)((char*)Xl + off) = lp;
        }
        CP_COMMIT(); CP_WAIT0();
        __syncthreads();

#pragma unroll
        for (int t = 0; t < 4; t++) {
            uint32_t Ah[4], Al[4];
            const uint32_t arow = mrow0 + (grp & 1) * 8 + wi;
            const uint32_t acol = t * 16 + (grp >> 1) * 8;
            ldm4(Ah, xh + 2 * SWZ(arow * 64 + acol));
            ldm4(Al, xl + 2 * SWZ(arow * 64 + acol));
#pragma unroll
            for (int pb = 0; pb < 4; pb++) {
                const uint32_t orow = ncol0 + pb * 16 + (grp >> 1) * 8 + wi;
                const uint32_t ocol = t * 16 + (grp & 1) * 8;
                uint32_t Bh[4], Bl[4];
                ldm4(Bh, wh + 2 * SWZ(orow * 64 + ocol));
                mma16816(C[2 * pb],     Ah, Bh);
                mma16816(C[2 * pb + 1], Ah, Bh + 2);
                mma16816(C[2 * pb],     Al, Bh);
                mma16816(C[2 * pb + 1], Al, Bh + 2);
                ldm4(Bl, wl + 2 * SWZ(orow * 64 + ocol));
                mma16816(C[2 * pb],     Ah, Bl);
                mma16816(C[2 * pb + 1], Ah, Bl + 2);
            }
        }
    }

    // ---- epilogue: bias, scale (log2e folded), split, scatter ----
    const int bb = row0 >> 11;
#pragma unroll
    for (int half = 0; half < 2; half++) {
        const int row = row0 + mrow0 + (lane >> 2) + half * 8;
        const int s   = row & 2047;
#pragma unroll
        for (int nb = 0; nb < 8; nb++) {
            const int col = ncol0 + nb * 8 + (lane & 3) * 2;
            float y0 = C[nb][2 * half]     + __ldg(bias + col);
            float y1 = C[nb][2 * half + 1] + __ldg(bias + col + 1);
            if (p == 0) { y0 *= QSCALE_F; y1 *= QSCALE_F; }
            else if (p == 1) { y0 *= LOG2E_F; y1 *= LOG2E_F; }
            __half h0, h1, l0, l1;
            split2(y0, h0, l0); split2(y1, h1, l1);
            const int hh = col >> 4, dd = col & 15;
            const size_t bhrow = ((size_t)(bb * H_ + hh) * S_ + s);
            const uint32_t hp = pack2(h0, h1);
            const uint32_t lp = pack2(l0, l1);
            switch (p) {
                case 0:
                    *(uint32_t*)(Qpack_d + bhrow * 64 + dd)      = hp;
                    *(uint32_t*)(Qpack_d + bhrow * 64 + 32 + dd) = lp;
                    break;
                case 1:
                    *(uint32_t*)(Qpack_d + bhrow * 64 + 16 + dd) = hp;
                    *(uint32_t*)(Qpack_d + bhrow * 64 + 48 + dd) = lp;
                    break;
                case 2:
                    *(uint32_t*)(Kpack_d + bhrow * 64 + dd)      = hp;
                    *(uint32_t*)(Kpack_d + bhrow * 64 + 32 + dd) = lp;
                    break;
                case 3:
                    *(uint32_t*)(Kpack_d + bhrow * 64 + 16 + dd) = hp;
                    *(uint32_t*)(Kpack_d + bhrow * 64 + 48 + dd) = lp;
                    break;
                default: {
                    const size_t vi0 = ((size_t)(bb * H_ + hh) * 16 + dd) * S_ + s;
                    const size_t vi1 = ((size_t)(bb * H_ + hh) * 16 + dd + 1) * S_ + s;
                    Vh_d[vi0] = h0; Vh_d[vi1] = h1;
                } break;
            }
        }
    }
}

// ---------------------------------------------------------------------------
// Kernel 2: HMMA flash attention — R12 exact (best known: 113.1us config).
// QK: hh + lh fp32-acc (32 mma, Kl never loaded).
// PV: Ph*Vh (8 mma) + row-sums via constant ones-column B-frag (4 mma).
// Softmax: fp32 exact max; P = ex2.approx.f16x2(pack(S - m)).
// ---------------------------------------------------------------------------
__global__ void __launch_bounds__(256, 2) flash_kernel()
{
    __shared__ __align__(1024) char Qs[16384];       // 128 rows x [Qh|Ql] 128B
    __shared__ __align__(1024) char Ks[2][8192];     // 64 keys x 128B rows (only Kh 64B used)
    __shared__ __align__(1024) char Vhs[2][2048];    // 16 vd x 64 keys fp16

    const int qt = blockIdx.x;
    const int bh = blockIdx.y;
    const int tid  = threadIdx.x;
    const int warp = tid >> 5;
    const int lane = tid & 31;
    const int grp  = lane >> 3;
    const int wi   = lane & 7;

    const uint32_t qs = smem_u32(Qs);
    const uint32_t ksb[2] = { smem_u32(Ks[0]),  smem_u32(Ks[1]) };
    const uint32_t vhb[2] = { smem_u32(Vhs[0]), smem_u32(Vhs[1]) };

    // constant B-fragment of the "ones column" (n=0 holders are lanes 0-3)
    const uint32_t onesv = (lane < 4) ? 0x3C003C00u : 0u;
    const uint32_t bones[2] = { onesv, onesv };

    {
        const __half* Qg = Qpack_d + ((size_t)bh * S_ + (size_t)qt * 128) * 64;
#pragma unroll
        for (int i = 0; i < 4; i++) {
            int e = tid + i * 256;
            cp16(qs + SWZ((e >> 3) * 128 + (e & 7) * 16), Qg + (size_t)e * 8);
        }
    }
#pragma unroll
    for (int pre = 0; pre < 2; pre++) {
        const __half* Kg = Kpack_d + ((size_t)bh * S_ + (size_t)pre * 64) * 64;
        {   // Kh halves only: 64 rows x 64B
            int r = tid >> 2, c = tid & 3;
            cp16(ksb[pre] + SWZ(r * 128 + c * 16), Kg + (size_t)r * 64 + c * 8);
        }
        if (tid < 128) {
            int r = tid >> 3, c = tid & 7;
            cp16(vhb[pre] + SWZ(r * 128 + c * 16),
                 Vh_d + ((size_t)bh * 16 + r) * S_ + (size_t)pre * 64 + c * 8);
        }
        CP_COMMIT();
    }

    CP_WAIT1();
    __syncthreads();

    uint32_t Aq[4][4];
#pragma unroll
    for (int t = 0; t < 4; t++) {
        const int row = warp * 16 + (grp & 1) * 8 + wi;
        const int ch  = t * 16 + (grp >> 1) * 8;
        ldm4(Aq[t], qs + SWZ(row * 128 + ch * 2));
    }

    float m0 = -1e30f, m1 = -1e30f;
    float Oc[2][4], Lc[4];
#pragma unroll
    for (int nb = 0; nb < 2; nb++)
#pragma unroll
        for (int j = 0; j < 4; j++) Oc[nb][j] = 0.f;
#pragma unroll
    for (int j = 0; j < 4; j++) Lc[j] = 0.f;

    for (int kt = 0; kt < S_ / 64; kt++) {
        const int buf = kt & 1;
        const uint32_t kss = ksb[buf];

        float Sc[8][4];
#pragma unroll
        for (int nb = 0; nb < 8; nb++)
#pragma unroll
            for (int j = 0; j < 4; j++) Sc[nb][j] = 0.f;

        // --- S = Qh*Kh + Ql*Kh ---
#pragma unroll
        for (int t = 0; t < 2; t++) {
#pragma unroll
            for (int p = 0; p < 4; p++) {
                const int key = p * 16 + (grp >> 1) * 8 + wi;
                uint32_t kb[4];
                ldm4(kb, kss + SWZ(key * 128 + (t * 16 + (grp & 1) * 8) * 2));
                mma16816(Sc[2 * p],     Aq[t],     kb);
                mma16816(Sc[2 * p + 1], Aq[t],     kb + 2);
                mma16816(Sc[2 * p],     Aq[t + 2], kb);
                mma16816(Sc[2 * p + 1], Aq[t + 2], kb + 2);
            }
        }

        // --- online softmax: exact fp32 row max ---
        float mx0 = -1e30f, mx1 = -1e30f;
#pragma unroll
        for (int nb = 0; nb < 8; nb++) {
            mx0 = fmaxf(mx0, fmaxf(Sc[nb][0], Sc[nb][1]));
            mx1 = fmaxf(mx1, fmaxf(Sc[nb][2], Sc[nb][3]));
        }
        mx0 = fmaxf(mx0, __shfl_xor_sync(0xffffffffu, mx0, 1));
        mx0 = fmaxf(mx0, __shfl_xor_sync(0xffffffffu, mx0, 2));
        mx1 = fmaxf(mx1, __shfl_xor_sync(0xffffffffu, mx1, 1));
        mx1 = fmaxf(mx1, __shfl_xor_sync(0xffffffffu, mx1, 2));

        const float mn0 = fmaxf(m0, mx0), mn1 = fmaxf(m1, mx1);
        const float c0 = ex2(m0 - mn0), c1 = ex2(m1 - mn1);
        m0 = mn0; m1 = mn1;

#pragma unroll
        for (int nb = 0; nb < 2; nb++) {
            Oc[nb][0] *= c0; Oc[nb][1] *= c0;
            Oc[nb][2] *= c1; Oc[nb][3] *= c1;
        }
        Lc[0] *= c0; Lc[2] *= c1;      // only cols held by lane&3==0 matter

        // --- P = exp2(S-m) via f16x2 MUFU; O += P*Vh ; Lc += P*ones ---
        const int vrow = (grp >> 1) * 8 + wi;
#pragma unroll
        for (int k2 = 0; k2 < 4; k2++) {
            uint32_t Pa[4];
#pragma unroll
            for (int h = 0; h < 2; h++) {
                const int nb = 2 * k2 + h;
                Pa[2 * h]     = ex2h2(packf2(Sc[nb][0] - mn0, Sc[nb][1] - mn0));
                Pa[2 * h + 1] = ex2h2(packf2(Sc[nb][2] - mn1, Sc[nb][3] - mn1));
            }
            uint32_t vb[4];
            ldm4(vb, vhb[buf] + SWZ(vrow * 128 + (k2 * 16 + (grp & 1) * 8) * 2));
            mma16816(Oc[0], Pa, vb);
            mma16816(Oc[1], Pa, vb + 2);
            mma16816(Lc, Pa, bones);
        }

        __syncthreads();
        if (kt + 2 < S_ / 64) {
            const __half* Kg = Kpack_d + ((size_t)bh * S_ + (size_t)(kt + 2) * 64) * 64;
            {
                int r = tid >> 2, c = tid & 3;
                cp16(ksb[buf] + SWZ(r * 128 + c * 16), Kg + (size_t)r * 64 + c * 8);
            }
            if (tid < 128) {
                int r = tid >> 3, c = tid & 7;
                cp16(vhb[buf] + SWZ(r * 128 + c * 16),
                     Vh_d + ((size_t)bh * 16 + r) * S_ + (size_t)(kt + 2) * 64 + c * 8);
            }
        }
        CP_COMMIT();
        if (kt + 1 < S_ / 64) {
            CP_WAIT1();
            __syncthreads();
        }
    }

    {
        // l for each row sits in Lc[0]/Lc[2] of the quad's lane&3==0 thread
        const float lr0 = __shfl_sync(0xffffffffu, Lc[0], lane & ~3);
        const float lr1 = __shfl_sync(0xffffffffu, Lc[2], lane & ~3);
        const float i0 = 1.0f / lr0, i1 = 1.0f / lr1;
        const int r0 = qt * 128 + warp * 16 + (lane >> 2);
        const int r1 = r0 + 8;
#pragma unroll
        for (int nb = 0; nb < 2; nb++) {
            const int col = nb * 8 + (lane & 3) * 2;
            float2* d0 = (float2*)(Od_d + ((size_t)bh * S_ + r0) * 16 + col);
            float2* d1 = (float2*)(Od_d + ((size_t)bh * S_ + r1) * 16 + col);
            *d0 = make_float2(Oc[nb][0] * i0, Oc[nb][1] * i0);
            *d1 = make_float2(Oc[nb][2] * i1, Oc[nb][3] * i1);
        }
    }
}

// ---------------------------------------------------------------------------
// Kernel 3: HMMA output projection, latency-optimized.
// 32-row blocks, 128 threads (4 warps: 2 row-groups x 2 col-groups), grid 256.
// Per-block work halves vs R12; >1 block/SM overlaps loads with mma.
// ---------------------------------------------------------------------------
__global__ void __launch_bounds__(128) outproj_kernel(
    const float* __restrict__ bo, float* __restrict__ out)
{
    __shared__ __align__(1024) __half Xh[32 * 64];    // 32 rows x 128B
    __shared__ __align__(1024) __half Xl[32 * 64];
    __shared__ __align__(1024) __half Wh[128 * 64];
    __shared__ __align__(1024) __half Wl[128 * 64];

    const int row0 = blockIdx.x * 32;
    const int bb = row0 >> 11;
    const int s0 = row0 & 2047;

    const int tid  = threadIdx.x;
    const int warp = tid >> 5;
    const int lane = tid & 31;
    const int grp  = lane >> 3;
    const int wi   = lane & 7;

    const uint32_t xh = smem_u32(Xh), xl = smem_u32(Xl);
    const uint32_t wh = smem_u32(Wh), wl = smem_u32(Wl);

    const int mrow0 = (warp >> 1) * 16;    // 2 row groups cover 32 rows
    const int ncol0 = (warp & 1) * 64;     // 2 col groups cover 128 cols

    float C[8][4];
#pragma unroll
    for (int nb = 0; nb < 8; nb++)
#pragma unroll
        for (int j = 0; j < 4; j++) C[nb][j] = 0.f;

    for (int kc = 0; kc < 2; kc++) {
        __syncthreads();
        // W chunk: 128 o-rows x 64 k halves = 1024 x 16B per buffer
#pragma unroll
        for (int it = 0; it < 8; it++) {
            const int e = tid + it * 128;            // 0..1023
            const int o = e >> 3, c = e & 7;
            cp16(wh + 2 * SWZ(o * 64 + c * 8), &Wsplit_d[3][o][0][kc * 64 + c * 8]);
            cp16(wl + 2 * SWZ(o * 64 + c * 8), &Wsplit_d[3][o][1][kc * 64 + c * 8]);
        }
        // X chunk: 32 rows x 64 cols = 512 float4
#pragma unroll
        for (int it = 0; it < 4; it++) {
            const int e = tid + it * 128;            // 0..511
            const int row = e >> 4, c4 = e & 15;
            const int col = kc * 64 + c4 * 4;
            const int hh = col >> 4, dd = col & 15;
            const float4 v = *(const float4*)(Od_d +
                (((size_t)(bb * H_ + hh) * S_) + s0 + row) * 16 + dd);
            __half h0, h1, h2, h3, l0, l1, l2, l3;
            split2(v.x, h0, l0); split2(v.y, h1, l1);
            split2(v.z, h2, l2); split2(v.w, h3, l3);
            uint2 hp, lp;
            hp.x = pack2(h0, h1);  hp.y = pack2(h2, h3);
            lp.x = pack2(l0, l1);  lp.y = pack2(l2, l3);
            const uint32_t off = 2 * SWZ(row * 64 + c4 * 4);
            *(uint2*)((char*)Xh + off) = hp;
            *(uint2*)((char*)Xl + off) = lp;
        }
        CP_COMMIT(); CP_WAIT0();
        __syncthreads();

#pragma unroll
        for (int t = 0; t < 4; t++) {
            uint32_t Ah[4], Al[4];
            const uint32_t arow = mrow0 + (grp & 1) * 8 + wi;
            const uint32_t acol = t * 16 + (grp >> 1) * 8;
            ldm4(Ah, xh + 2 * SWZ(arow * 64 + acol));
            ldm4(Al, xl + 2 * SWZ(arow * 64 + acol));
#pragma unroll
            for (int pb = 0; pb < 4; pb++) {
                const uint32_t orow = ncol0 + pb * 16 + (grp >> 1) * 8 + wi;
                const uint32_t ocol = t * 16 + (grp & 1) * 8;
                uint32_t Bh[4], Bl[4];
                ldm4(Bh, wh + 2 * SWZ(orow * 64 + ocol));
                mma16816(C[2 * pb],     Ah, Bh);
                mma16816(C[2 * pb + 1], Ah, Bh + 2);
                mma16816(C[2 * pb],     Al, Bh);
                mma16816(C[2 * pb + 1], Al, Bh + 2);
                ldm4(Bl, wl + 2 * SWZ(orow * 64 + ocol));
                mma16816(C[2 * pb],     Ah, Bl);
                mma16816(C[2 * pb + 1], Ah, Bl + 2);
            }
        }
    }

#pragma unroll
    for (int half = 0; half < 2; half++) {
        const int row = row0 + mrow0 + (lane >> 2) + half * 8;
#pragma unroll
        for (int nb = 0; nb < 8; nb++) {
            const int col = ncol0 + nb * 8 + (lane & 3) * 2;
            float2* dst = (float2*)(out + (size_t)row * 128 + col);
            *dst = make_float2(C[nb][2 * half]     + __ldg(bo + col),
                               C[nb][2 * half + 1] + __ldg(bo + col + 1));
        }
    }
}

// ---------------------------------------------------------------------------
extern "C" void kernel_launch(void* const* d_in, const int* in_sizes, int n_in,
                              void* d_out, int out_size)
{
    const float* query = (const float*)d_in[0];
    const float* key   = (const float*)d_in[1];
    const float* value = (const float*)d_in[2];
    const float* pos   = (const float*)d_in[3];
    const float* W0    = (const float*)d_in[4];
    const float* b0    = (const float*)d_in[5];
    const float* W1    = (const float*)d_in[6];
    const float* b1    = (const float*)d_in[7];
    const float* W2    = (const float*)d_in[8];
    const float* b2    = (const float*)d_in[9];
    const float* Wo    = (const float*)d_in[10];
    const float* bo    = (const float*)d_in[11];
    float* out = (float*)d_out;

    prep_kernel<<<256, 256>>>(W0, W1, W2, Wo);
    proj_kernel<<<dim3((B_ * S_) / 64, 5), 256>>>(query, key, value, pos, b0, b1, b2);
    flash_kernel<<<dim3(S_ / 128, BH_), 256>>>();
    outproj_kernel<<<(B_ * S_) / 32, 128>>>(bo, out);
}

// round 16
// speedup vs baseline: 1.1779x; 1.1190x over previous
#include <cuda_runtime.h>
#include <cuda_fp16.h>
#include <cstdint>

// Problem constants
#define B_    4
#define S_    2048
#define H_    8
#define BH_   (B_*H_)       // 32

// log2(e) folded into q/pos_q at projection time (softmax in exp2 domain)
#define LOG2E_F      1.4426950408889634f
#define QSCALE_F     0.36067376022224085f   // 0.25 * log2(e)

// Packed split-fp16 intermediates (static device scratch)
__device__ __align__(256) __half Qpack_d[(size_t)BH_ * S_ * 64];  // [bh][s][Qh(32)|Ql(32)]
__device__ __align__(256) __half Kpack_d[(size_t)BH_ * S_ * 64];  // [bh][key][Kh(32)|Kl(32)]
__device__ __align__(256) __half Vh_d[(size_t)BH_ * 16 * S_];     // [bh][vd][key]
__device__ __align__(256) float  Od_d[(size_t)BH_ * S_ * 16];     // [bh][s][16]
__device__ __align__(256) __half Wsplit_d[4][128][2][128];        // [w][o][hi/lo][k]

// ---------------------------------------------------------------------------
// PTX helpers (baseline features only — compute_103-safe)
// ---------------------------------------------------------------------------
__device__ __forceinline__ uint32_t smem_u32(const void* p) {
    uint32_t a;
    asm("{ .reg .u64 t; cvta.to.shared.u64 t, %1; cvt.u32.u64 %0, t; }" : "=r"(a) : "l"(p));
    return a;
}
__device__ __forceinline__ void cp16(uint32_t d, const void* s) {
    asm volatile("cp.async.cg.shared.global [%0], [%1], 16;" :: "r"(d), "l"(s));
}
#define CP_COMMIT() asm volatile("cp.async.commit_group;" ::: "memory")
#define CP_WAIT1()  asm volatile("cp.async.wait_group 1;" ::: "memory")
#define CP_WAIT0()  asm volatile("cp.async.wait_group 0;" ::: "memory")

__device__ __forceinline__ void ldm4(uint32_t* r, uint32_t addr) {
    asm volatile("ldmatrix.sync.aligned.m8n8.x4.shared.b16 {%0,%1,%2,%3}, [%4];"
        : "=r"(r[0]), "=r"(r[1]), "=r"(r[2]), "=r"(r[3]) : "r"(addr));
}
__device__ __forceinline__ void mma16816(float* d, const uint32_t* a, const uint32_t* b) {
    asm volatile("mma.sync.aligned.m16n8k16.row.col.f32.f16.f16.f32 "
        "{%0,%1,%2,%3}, {%4,%5,%6,%7}, {%8,%9}, {%0,%1,%2,%3};"
        : "+f"(d[0]), "+f"(d[1]), "+f"(d[2]), "+f"(d[3])
        : "r"(a[0]), "r"(a[1]), "r"(a[2]), "r"(a[3]), "r"(b[0]), "r"(b[1]));
}
__device__ __forceinline__ float ex2(float x) {
    float y;
    asm("ex2.approx.ftz.f32 %0, %1;" : "=f"(y) : "f"(x));
    return y;
}
// packed half2 exp2 — one MUFU for two P values, result already in mma layout
__device__ __forceinline__ uint32_t ex2h2(uint32_t x) {
    uint32_t y;
    asm("ex2.approx.f16x2 %0, %1;" : "=r"(y) : "r"(x));
    return y;
}

#define SWZ(x) ((x) ^ (((x) >> 3) & 0x70))

__device__ __forceinline__ void split2(float x, __half& hi, __half& lo) {
    hi = __float2half_rn(x);
    lo = __float2half_rn(x - __half2float(hi));
}
__device__ __forceinline__ uint32_t pack2(__half a, __half b) {
    __half2 t = __halves2half2(a, b);
    return *reinterpret_cast<uint32_t*>(&t);
}
__device__ __forceinline__ uint32_t packf2(float a, float b) {
    __half2 t = __floats2half2_rn(a, b);
    return *reinterpret_cast<uint32_t*>(&t);
}

// ---------------------------------------------------------------------------
// Kernel 0: split W0/W1/W2/Wo into fp16 hi/lo pairs.
// ---------------------------------------------------------------------------
__global__ void __launch_bounds__(256) prep_kernel(
    const float* __restrict__ W0, const float* __restrict__ W1,
    const float* __restrict__ W2, const float* __restrict__ Wo)
{
    const int idx = blockIdx.x * 256 + threadIdx.x;   // 0 .. 65535
    const int w = idx >> 14;
    const int o = (idx >> 7) & 127;
    const int k = idx & 127;
    const float* W = (w == 0) ? W0 : (w == 1) ? W1 : (w == 2) ? W2 : Wo;
    __half hi, lo;
    split2(W[o * 128 + k], hi, lo);
    Wsplit_d[w][o][0][k] = hi;
    Wsplit_d[w][o][1][k] = lo;
}

// ---------------------------------------------------------------------------
// Kernel 1: HMMA projections (split-fp16, 3 chains).
//   p=0: query@W0^T *0.25*log2e -> Q dims 0-15   p=1: pos@W0^T *log2e -> Q dims 16-31
//   p=2: key  @W1^T             -> K dims 0-15   p=3: pos@W1^T        -> K dims 16-31
//   p=4: value@W2^T             -> Vh (transposed, hi only)
// ---------------------------------------------------------------------------
__global__ void __launch_bounds__(256) proj_kernel(
    const float* __restrict__ query, const float* __restrict__ key,
    const float* __restrict__ value, const float* __restrict__ pos,
    const float* __restrict__ b0, const float* __restrict__ b1,
    const float* __restrict__ b2)
{
    __shared__ __align__(1024) __half Xh[64 * 64];    // 64 rows x 128B
    __shared__ __align__(1024) __half Xl[64 * 64];
    __shared__ __align__(1024) __half Wh[128 * 64];   // 128 o x 128B
    __shared__ __align__(1024) __half Wl[128 * 64];

    const int p = blockIdx.y;
    const float* X = (p == 0) ? query : (p == 1 || p == 3) ? pos : (p == 2) ? key : value;
    const float* bias = (p < 2) ? b0 : (p < 4) ? b1 : b2;
    const int wsel = (p < 2) ? 0 : (p < 4) ? 1 : 2;

    const int row0 = blockIdx.x * 64;
    const int tid  = threadIdx.x;
    const int warp = tid >> 5;
    const int lane = tid & 31;
    const int grp  = lane >> 3;
    const int wi   = lane & 7;

    const uint32_t xh = smem_u32(Xh), xl = smem_u32(Xl);
    const uint32_t wh = smem_u32(Wh), wl = smem_u32(Wl);

    const int mrow0 = (warp >> 1) * 16;     // warp row base within tile
    const int ncol0 = (warp & 1) * 64;      // warp col base

    float C[8][4];
#pragma unroll
    for (int nb = 0; nb < 8; nb++)
#pragma unroll
        for (int j = 0; j < 4; j++) C[nb][j] = 0.f;

    for (int kc = 0; kc < 2; kc++) {
        __syncthreads();
#pragma unroll
        for (int it = 0; it < 4; it++) {
            const int e = tid + it * 256;            // 0..1023
            const int o = e >> 3, c = e & 7;
            cp16(wh + 2 * SWZ(o * 64 + c * 8), &Wsplit_d[wsel][o][0][kc * 64 + c * 8]);
            cp16(wl + 2 * SWZ(o * 64 + c * 8), &Wsplit_d[wsel][o][1][kc * 64 + c * 8]);
        }
#pragma unroll
        for (int it = 0; it < 4; it++) {
            const int e = tid + it * 256;            // 0..1023 float4s
            const int row = e >> 4, c4 = e & 15;
            const float4 v = *(const float4*)(X + (size_t)(row0 + row) * 128 + kc * 64 + c4 * 4);
            __half h0, h1, h2, h3, l0, l1, l2, l3;
            split2(v.x, h0, l0); split2(v.y, h1, l1);
            split2(v.z, h2, l2); split2(v.w, h3, l3);
            uint2 hp, lp;
            hp.x = pack2(h0, h1);  hp.y = pack2(h2, h3);
            lp.x = pack2(l0, l1);  lp.y = pack2(l2, l3);
            const uint32_t off = 2 * SWZ(row * 64 + c4 * 4);
            *(uint2*)((char*)Xh + off) = hp;
            *(uint2*)((char*)Xl + off) = lp;
        }
        CP_COMMIT(); CP_WAIT0();
        __syncthreads();

#pragma unroll
        for (int t = 0; t < 4; t++) {
            uint32_t Ah[4], Al[4];
            const uint32_t arow = mrow0 + (grp & 1) * 8 + wi;
            const uint32_t acol = t * 16 + (grp >> 1) * 8;
            ldm4(Ah, xh + 2 * SWZ(arow * 64 + acol));
            ldm4(Al, xl + 2 * SWZ(arow * 64 + acol));
#pragma unroll
            for (int pb = 0; pb < 4; pb++) {
                const uint32_t orow = ncol0 + pb * 16 + (grp >> 1) * 8 + wi;
                const uint32_t ocol = t * 16 + (grp & 1) * 8;
                uint32_t Bh[4], Bl[4];
                ldm4(Bh, wh + 2 * SWZ(orow * 64 + ocol));
                mma16816(C[2 * pb],     Ah, Bh);
                mma16816(C[2 * pb + 1], Ah, Bh + 2);
                mma16816(C[2 * pb],     Al, Bh);
                mma16816(C[2 * pb + 1], Al, Bh + 2);
                ldm4(Bl, wl + 2 * SWZ(orow * 64 + ocol));
                mma16816(C[2 * pb],     Ah, Bl);
                mma16816(C[2 * pb + 1], Ah, Bl + 2);
            }
        }
    }

    // ---- epilogue: bias, scale (log2e folded), split, scatter ----
    const int bb = row0 >> 11;
#pragma unroll
    for (int half = 0; half < 2; half++) {
        const int row = row0 + mrow0 + (lane >> 2) + half * 8;
        const int s   = row & 2047;
#pragma unroll
        for (int nb = 0; nb < 8; nb++) {
            const int col = ncol0 + nb * 8 + (lane & 3) * 2;
            float y0 = C[nb][2 * half]     + __ldg(bias + col);
            float y1 = C[nb][2 * half + 1] + __ldg(bias + col + 1);
            if (p == 0) { y0 *= QSCALE_F; y1 *= QSCALE_F; }
            else if (p == 1) { y0 *= LOG2E_F; y1 *= LOG2E_F; }
            __half h0, h1, l0, l1;
            split2(y0, h0, l0); split2(y1, h1, l1);
            const int hh = col >> 4, dd = col & 15;
            const size_t bhrow = ((size_t)(bb * H_ + hh) * S_ + s);
            const uint32_t hp = pack2(h0, h1);
            const uint32_t lp = pack2(l0, l1);
            switch (p) {
                case 0:
                    *(uint32_t*)(Qpack_d + bhrow * 64 + dd)      = hp;
                    *(uint32_t*)(Qpack_d + bhrow * 64 + 32 + dd) = lp;
                    break;
                case 1:
                    *(uint32_t*)(Qpack_d + bhrow * 64 + 16 + dd) = hp;
                    *(uint32_t*)(Qpack_d + bhrow * 64 + 48 + dd) = lp;
                    break;
                case 2:
                    *(uint32_t*)(Kpack_d + bhrow * 64 + dd)      = hp;
                    *(uint32_t*)(Kpack_d + bhrow * 64 + 32 + dd) = lp;
                    break;
                case 3:
                    *(uint32_t*)(Kpack_d + bhrow * 64 + 16 + dd) = hp;
                    *(uint32_t*)(Kpack_d + bhrow * 64 + 48 + dd) = lp;
                    break;
                default: {
                    const size_t vi0 = ((size_t)(bb * H_ + hh) * 16 + dd) * S_ + s;
                    const size_t vi1 = ((size_t)(bb * H_ + hh) * 16 + dd + 1) * S_ + s;
                    Vh_d[vi0] = h0; Vh_d[vi1] = h1;
                } break;
            }
        }
    }
}

// ---------------------------------------------------------------------------
// Kernel 2: HMMA flash attention — R12 per-warp math at 5 CTAs/SM.
// 64-row q-tiles, 128 threads (4 warps x 16 rows), __launch_bounds__(128,5):
// reg cap 102 > ~95 demand (no R13-style spills), per-warp tile work identical
// to R12 (no R14-style overhead).  Q staged via overlay in the K ring space.
// QK: hh + lh fp32-acc (32 mma).  PV: Ph*Vh + ones-frag Lc (12 mma).
// Softmax: fp32 exact max; P = ex2.approx.f16x2.
// ---------------------------------------------------------------------------
__global__ void __launch_bounds__(128, 5) flash_kernel()
{
    // Unified 20.5KB buffer:
    //   prologue: Q tile (64 rows x 128B = 8KB) occupies [0, 8192)
    //   mainloop: K0 [0,8192) K1 [8192,16384) V0 [16384,18432) V1 [18432,20480)
    __shared__ __align__(1024) char Smem[20480];

    const int qt = blockIdx.x;      // 0..31 (64-row q-tiles)
    const int bh = blockIdx.y;
    const int tid  = threadIdx.x;
    const int warp = tid >> 5;
    const int lane = tid & 31;
    const int grp  = lane >> 3;
    const int wi   = lane & 7;

    const uint32_t sbase = smem_u32(Smem);
    const uint32_t ksb[2] = { sbase,         sbase + 8192 };
    const uint32_t vhb[2] = { sbase + 16384, sbase + 18432 };

    const __half* Kg0 = Kpack_d + (size_t)bh * S_ * 64;
    const __half* Vg0 = Vh_d + ((size_t)bh * 16) * S_;

    // constant B-fragment of the "ones column" (n=0 holders are lanes 0-3)
    const uint32_t onesv = (lane < 4) ? 0x3C003C00u : 0u;
    const uint32_t bones[2] = { onesv, onesv };

    // ---- stage 1: Q (64x128B) into ring space, consume into registers ----
    {
        const __half* Qg = Qpack_d + ((size_t)bh * S_ + (size_t)qt * 64) * 64;
#pragma unroll
        for (int i = 0; i < 4; i++) {
            int e = tid + i * 128;               // 0..511 c16s
            cp16(sbase + SWZ((e >> 3) * 128 + (e & 7) * 16), Qg + (size_t)e * 8);
        }
        CP_COMMIT(); CP_WAIT0();
        __syncthreads();
    }

    uint32_t Aq[4][4];
#pragma unroll
    for (int t = 0; t < 4; t++) {
        const int row = warp * 16 + (grp & 1) * 8 + wi;
        const int ch  = t * 16 + (grp >> 1) * 8;
        ldm4(Aq[t], sbase + SWZ(row * 128 + ch * 2));
    }
    __syncthreads();     // every warp done reading Q before rings overwrite it

    // ---- stage 2: prefetch K/V 64-key tiles 0,1 ----
#pragma unroll
    for (int pre = 0; pre < 2; pre++) {
        const __half* Kg = Kg0 + (size_t)pre * 64 * 64;
#pragma unroll
        for (int i = 0; i < 2; i++) {            // Kh: 64 rows x 4 c16 = 256
            int e = tid + i * 128;
            cp16(ksb[pre] + SWZ((e >> 2) * 128 + (e & 3) * 16), Kg + (size_t)(e >> 2) * 64 + (e & 3) * 8);
        }
        if (tid < 128) {                          // V: 16 rows x 8 c16 = 128
            int r = tid >> 3, c = tid & 7;
            cp16(vhb[pre] + SWZ(r * 128 + c * 16),
                 Vg0 + (size_t)r * S_ + (size_t)pre * 64 + c * 8);
        }
        CP_COMMIT();
    }

    CP_WAIT1();          // tile0 resident
    __syncthreads();

    float m0 = -1e30f, m1 = -1e30f;
    float Oc[2][4], Lc[4];
#pragma unroll
    for (int nb = 0; nb < 2; nb++)
#pragma unroll
        for (int j = 0; j < 4; j++) Oc[nb][j] = 0.f;
#pragma unroll
    for (int j = 0; j < 4; j++) Lc[j] = 0.f;

    for (int kt = 0; kt < S_ / 64; kt++) {
        const int buf = kt & 1;
        const uint32_t kss = ksb[buf];

        float Sc[8][4];
#pragma unroll
        for (int nb = 0; nb < 8; nb++)
#pragma unroll
            for (int j = 0; j < 4; j++) Sc[nb][j] = 0.f;

        // --- S = Qh*Kh + Ql*Kh ---
#pragma unroll
        for (int t = 0; t < 2; t++) {
#pragma unroll
            for (int p = 0; p < 4; p++) {
                const int key = p * 16 + (grp >> 1) * 8 + wi;
                uint32_t kb[4];
                ldm4(kb, kss + SWZ(key * 128 + (t * 16 + (grp & 1) * 8) * 2));
                mma16816(Sc[2 * p],     Aq[t],     kb);
                mma16816(Sc[2 * p + 1], Aq[t],     kb + 2);
                mma16816(Sc[2 * p],     Aq[t + 2], kb);
                mma16816(Sc[2 * p + 1], Aq[t + 2], kb + 2);
            }
        }

        // --- online softmax: exact fp32 row max ---
        float mx0 = -1e30f, mx1 = -1e30f;
#pragma unroll
        for (int nb = 0; nb < 8; nb++) {
            mx0 = fmaxf(mx0, fmaxf(Sc[nb][0], Sc[nb][1]));
            mx1 = fmaxf(mx1, fmaxf(Sc[nb][2], Sc[nb][3]));
        }
        mx0 = fmaxf(mx0, __shfl_xor_sync(0xffffffffu, mx0, 1));
        mx0 = fmaxf(mx0, __shfl_xor_sync(0xffffffffu, mx0, 2));
        mx1 = fmaxf(mx1, __shfl_xor_sync(0xffffffffu, mx1, 1));
        mx1 = fmaxf(mx1, __shfl_xor_sync(0xffffffffu, mx1, 2));

        const float mn0 = fmaxf(m0, mx0), mn1 = fmaxf(m1, mx1);
        const float c0 = ex2(m0 - mn0), c1 = ex2(m1 - mn1);
        m0 = mn0; m1 = mn1;

#pragma unroll
        for (int nb = 0; nb < 2; nb++) {
            Oc[nb][0] *= c0; Oc[nb][1] *= c0;
            Oc[nb][2] *= c1; Oc[nb][3] *= c1;
        }
        Lc[0] *= c0; Lc[2] *= c1;      // only cols held by lane&3==0 matter

        // --- P = exp2(S-m) via f16x2 MUFU; O += P*Vh ; Lc += P*ones ---
        const int vrow = (grp >> 1) * 8 + wi;
#pragma unroll
        for (int k2 = 0; k2 < 4; k2++) {
            uint32_t Pa[4];
#pragma unroll
            for (int h = 0; h < 2; h++) {
                const int nb = 2 * k2 + h;
                Pa[2 * h]     = ex2h2(packf2(Sc[nb][0] - mn0, Sc[nb][1] - mn0));
                Pa[2 * h + 1] = ex2h2(packf2(Sc[nb][2] - mn1, Sc[nb][3] - mn1));
            }
            uint32_t vb[4];
            ldm4(vb, vhb[buf] + SWZ(vrow * 128 + (k2 * 16 + (grp & 1) * 8) * 2));
            mma16816(Oc[0], Pa, vb);
            mma16816(Oc[1], Pa, vb + 2);
            mma16816(Lc, Pa, bones);
        }

        __syncthreads();
        if (kt + 2 < S_ / 64) {
            const __half* Kg = Kg0 + (size_t)(kt + 2) * 64 * 64;
#pragma unroll
            for (int i = 0; i < 2; i++) {
                int e = tid + i * 128;
                cp16(ksb[buf] + SWZ((e >> 2) * 128 + (e & 3) * 16),
                     Kg + (size_t)(e >> 2) * 64 + (e & 3) * 8);
            }
            if (tid < 128) {
                int r = tid >> 3, c = tid & 7;
                cp16(vhb[buf] + SWZ(r * 128 + c * 16),
                     Vg0 + (size_t)r * S_ + (size_t)(kt + 2) * 64 + c * 8);
            }
        }
        CP_COMMIT();
        if (kt + 1 < S_ / 64) {
            CP_WAIT1();
            __syncthreads();
        }
    }

    {
        // l for each row sits in Lc[0]/Lc[2] of the quad's lane&3==0 thread
        const float lr0 = __shfl_sync(0xffffffffu, Lc[0], lane & ~3);
        const float lr1 = __shfl_sync(0xffffffffu, Lc[2], lane & ~3);
        const float i0 = 1.0f / lr0, i1 = 1.0f / lr1;
        const int r0 = qt * 64 + warp * 16 + (lane >> 2);
        const int r1 = r0 + 8;
#pragma unroll
        for (int nb = 0; nb < 2; nb++) {
            const int col = nb * 8 + (lane & 3) * 2;
            float2* d0 = (float2*)(Od_d + ((size_t)bh * S_ + r0) * 16 + col);
            float2* d1 = (float2*)(Od_d + ((size_t)bh * S_ + r1) * 16 + col);
            *d0 = make_float2(Oc[nb][0] * i0, Oc[nb][1] * i0);
            *d1 = make_float2(Oc[nb][2] * i1, Oc[nb][3] * i1);
        }
    }
}

// ---------------------------------------------------------------------------
// Kernel 3: HMMA output projection, latency-optimized (R15 version).
// 32-row blocks, 128 threads, grid 256.
// ---------------------------------------------------------------------------
__global__ void __launch_bounds__(128) outproj_kernel(
    const float* __restrict__ bo, float* __restrict__ out)
{
    __shared__ __align__(1024) __half Xh[32 * 64];    // 32 rows x 128B
    __shared__ __align__(1024) __half Xl[32 * 64];
    __shared__ __align__(1024) __half Wh[128 * 64];
    __shared__ __align__(1024) __half Wl[128 * 64];

    const int row0 = blockIdx.x * 32;
    const int bb = row0 >> 11;
    const int s0 = row0 & 2047;

    const int tid  = threadIdx.x;
    const int warp = tid >> 5;
    const int lane = tid & 31;
    const int grp  = lane >> 3;
    const int wi   = lane & 7;

    const uint32_t xh = smem_u32(Xh), xl = smem_u32(Xl);
    const uint32_t wh = smem_u32(Wh), wl = smem_u32(Wl);

    const int mrow0 = (warp >> 1) * 16;    // 2 row groups cover 32 rows
    const int ncol0 = (warp & 1) * 64;     // 2 col groups cover 128 cols

    float C[8][4];
#pragma unroll
    for (int nb = 0; nb < 8; nb++)
#pragma unroll
        for (int j = 0; j < 4; j++) C[nb][j] = 0.f;

    for (int kc = 0; kc < 2; kc++) {
        __syncthreads();
#pragma unroll
        for (int it = 0; it < 8; it++) {
            const int e = tid + it * 128;            // 0..1023
            const int o = e >> 3, c = e & 7;
            cp16(wh + 2 * SWZ(o * 64 + c * 8), &Wsplit_d[3][o][0][kc * 64 + c * 8]);
            cp16(wl + 2 * SWZ(o * 64 + c * 8), &Wsplit_d[3][o][1][kc * 64 + c * 8]);
        }
#pragma unroll
        for (int it = 0; it < 4; it++) {
            const int e = tid + it * 128;            // 0..511
            const int row = e >> 4, c4 = e & 15;
            const int col = kc * 64 + c4 * 4;
            const int hh = col >> 4, dd = col & 15;
            const float4 v = *(const float4*)(Od_d +
                (((size_t)(bb * H_ + hh) * S_) + s0 + row) * 16 + dd);
            __half h0, h1, h2, h3, l0, l1, l2, l3;
            split2(v.x, h0, l0); split2(v.y, h1, l1);
            split2(v.z, h2, l2); split2(v.w, h3, l3);
            uint2 hp, lp;
            hp.x = pack2(h0, h1);  hp.y = pack2(h2, h3);
            lp.x = pack2(l0, l1);  lp.y = pack2(l2, l3);
            const uint32_t off = 2 * SWZ(row * 64 + c4 * 4);
            *(uint2*)((char*)Xh + off) = hp;
            *(uint2*)((char*)Xl + off) = lp;
        }
        CP_COMMIT(); CP_WAIT0();
        __syncthreads();

#pragma unroll
        for (int t = 0; t < 4; t++) {
            uint32_t Ah[4], Al[4];
            const uint32_t arow = mrow0 + (grp & 1) * 8 + wi;
            const uint32_t acol = t * 16 + (grp >> 1) * 8;
            ldm4(Ah, xh + 2 * SWZ(arow * 64 + acol));
            ldm4(Al, xl + 2 * SWZ(arow * 64 + acol));
#pragma unroll
            for (int pb = 0; pb < 4; pb++) {
                const uint32_t orow = ncol0 + pb * 16 + (grp >> 1) * 8 + wi;
                const uint32_t ocol = t * 16 + (grp & 1) * 8;
                uint32_t Bh[4], Bl[4];
                ldm4(Bh, wh + 2 * SWZ(orow * 64 + ocol));
                mma16816(C[2 * pb],     Ah, Bh);
                mma16816(C[2 * pb + 1], Ah, Bh + 2);
                mma16816(C[2 * pb],     Al, Bh);
                mma16816(C[2 * pb + 1], Al, Bh + 2);
                ldm4(Bl, wl + 2 * SWZ(orow * 64 + ocol));
                mma16816(C[2 * pb],     Ah, Bl);
                mma16816(C[2 * pb + 1], Ah, Bl + 2);
            }
        }
    }

#pragma unroll
    for (int half = 0; half < 2; half++) {
        const int row = row0 + mrow0 + (lane >> 2) + half * 8;
#pragma unroll
        for (int nb = 0; nb < 8; nb++) {
            const int col = ncol0 + nb * 8 + (lane & 3) * 2;
            float2* dst = (float2*)(out + (size_t)row * 128 + col);
            *dst = make_float2(C[nb][2 * half]     + __ldg(bo + col),
                               C[nb][2 * half + 1] + __ldg(bo + col + 1));
        }
    }
}

// ---------------------------------------------------------------------------
extern "C" void kernel_launch(void* const* d_in, const int* in_sizes, int n_in,
                              void* d_out, int out_size)
{
    const float* query = (const float*)d_in[0];
    const float* key   = (const float*)d_in[1];
    const float* value = (const float*)d_in[2];
    const float* pos   = (const float*)d_in[3];
    const float* W0    = (const float*)d_in[4];
    const float* b0    = (const float*)d_in[5];
    const float* W1    = (const float*)d_in[6];
    const float* b1    = (const float*)d_in[7];
    const float* W2    = (const float*)d_in[8];
    const float* b2    = (const float*)d_in[9];
    const float* Wo    = (const float*)d_in[10];
    const float* bo    = (const float*)d_in[11];
    float* out = (float*)d_out;

    prep_kernel<<<256, 256>>>(W0, W1, W2, Wo);
    proj_kernel<<<dim3((B_ * S_) / 64, 5), 256>>>(query, key, value, pos, b0, b1, b2);
    flash_kernel<<<dim3(S_ / 64, BH_), 128>>>();
    outproj_kernel<<<(B_ * S_) / 32, 128>>>(bo, out);
}